// round 5
// baseline (speedup 1.0000x reference)
#include <cuda_runtime.h>
#include <cuda_bf16.h>
#include <cstdint>

// Problem constants
#define BB 2
#define MM 4096
#define CC 256
#define HH 64
#define WW 64
#define NLVL 4
#define RAD 4
#define SIDE 9          // 2*RAD+1
#define OUTCH (NLVL * SIDE * SIDE)   // 324

// Pyramid (pixel-major: [b][level][y][x][c]) in float
#define OFF0 0
#define OFF1 (4096 * 256)
#define OFF2 ((4096 + 1024) * 256)
#define OFF3 ((4096 + 1024 + 256) * 256)
#define BSTR ((4096 + 1024 + 256 + 64) * 256)
#define PYR_TOTAL (BB * BSTR)

__device__ float4 g_pyr4[PYR_TOTAL / 4];     // 11.1 MB static scratch
__device__ int g_binCnt[512];
__device__ int g_binOff[512];
__device__ int g_perm[BB * MM];

// ---------------------------------------------------------------------------
// packed f32x2 helpers
// ---------------------------------------------------------------------------
__device__ __forceinline__ unsigned long long pk(float x, float y) {
    unsigned long long r;
    asm("mov.b64 %0, {%1, %2};" : "=l"(r) : "f"(x), "f"(y));
    return r;
}
__device__ __forceinline__ float2 upk(unsigned long long v) {
    float2 f;
    asm("mov.b64 {%0, %1}, %2;" : "=f"(f.x), "=f"(f.y) : "l"(v));
    return f;
}
__device__ __forceinline__ void ffma2(unsigned long long& acc,
                                      unsigned long long a,
                                      unsigned long long b) {
    asm("fma.rn.f32x2 %0, %1, %2, %3;" : "=l"(acc) : "l"(a), "l"(b), "l"(acc));
}

// ---------------------------------------------------------------------------
// Kernel A1: transpose fmap2 (b, c, p) -> pyramid level 0 (b, p, c)
// ---------------------------------------------------------------------------
__global__ void transpose_l0_kernel(const float* __restrict__ fmap2) {
    __shared__ float tile[32][33];
    float* g = reinterpret_cast<float*>(g_pyr4);
    int b  = blockIdx.z;
    int c0 = blockIdx.y * 32;
    int p0 = blockIdx.x * 32;
    const float* in_b = fmap2 + (size_t)b * CC * (HH * WW);
    #pragma unroll
    for (int r = threadIdx.y; r < 32; r += 8)
        tile[r][threadIdx.x] = in_b[(size_t)(c0 + r) * (HH * WW) + p0 + threadIdx.x];
    __syncthreads();
    float* out_b = g + (size_t)b * BSTR;
    #pragma unroll
    for (int r = threadIdx.y; r < 32; r += 8)
        out_b[(size_t)(p0 + r) * CC + c0 + threadIdx.x] = tile[threadIdx.x][r];
}

// ---------------------------------------------------------------------------
// Kernel A2: 2x2 average pool, pixel-major
// ---------------------------------------------------------------------------
__global__ void pool_kernel(int inOff, int outOff, int Wi, int Wo, int total) {
    float* g = reinterpret_cast<float*>(g_pyr4);
    int tid = blockIdx.x * blockDim.x + threadIdx.x;
    if (tid >= total) return;
    int c = tid & (CC - 1);
    int idx = tid >> 8;
    int x = idx % Wo; idx /= Wo;
    int y = idx % Wo; idx /= Wo;
    int b = idx;
    const float* ib = g + (size_t)b * BSTR + inOff;
    float v = 0.25f * (ib[((size_t)(2 * y)     * Wi + 2 * x)     * CC + c] +
                       ib[((size_t)(2 * y)     * Wi + 2 * x + 1) * CC + c] +
                       ib[((size_t)(2 * y + 1) * Wi + 2 * x)     * CC + c] +
                       ib[((size_t)(2 * y + 1) * Wi + 2 * x + 1) * CC + c]);
    g[(size_t)b * BSTR + outOff + ((size_t)y * Wo + x) * CC + c] = v;
}

// ---------------------------------------------------------------------------
// Sorting: bin points by 4x4-pixel cell of their centroid (16x16 bins/batch)
// ---------------------------------------------------------------------------
__device__ __forceinline__ int point_bin(const float* cents, int pt) {
    float cx = cents[(size_t)pt * 2 + 0];
    float cy = cents[(size_t)pt * 2 + 1];
    int bx = min(15, max(0, ((int)cx) >> 2));
    int by = min(15, max(0, ((int)cy) >> 2));
    return ((pt >> 12) << 8) + by * 16 + bx;
}

__global__ void zero_bins_kernel() {
    int t = blockIdx.x * blockDim.x + threadIdx.x;
    if (t < 512) g_binCnt[t] = 0;
}

__global__ void count_kernel(const float* __restrict__ cents) {
    int pt = blockIdx.x * blockDim.x + threadIdx.x;
    if (pt >= BB * MM) return;
    atomicAdd(&g_binCnt[point_bin(cents, pt)], 1);
}

__global__ void scan_kernel() {
    __shared__ int s[512];
    int t = threadIdx.x;
    s[t] = g_binCnt[t];
    __syncthreads();
    #pragma unroll
    for (int d = 1; d < 512; d <<= 1) {
        int v = (t >= d) ? s[t - d] : 0;
        __syncthreads();
        s[t] += v;
        __syncthreads();
    }
    g_binOff[t] = s[t] - g_binCnt[t];   // exclusive prefix
}

__global__ void scatter_kernel(const float* __restrict__ cents) {
    int pt = blockIdx.x * blockDim.x + threadIdx.x;
    if (pt >= BB * MM) return;
    int pos = atomicAdd(&g_binOff[point_bin(cents, pt)], 1);
    g_perm[pos] = pt;
}

// ---------------------------------------------------------------------------
// Kernel B: one warp per point (points in spatially-sorted order).
// Lane owns 8 channels (2 x float4 -> 4 packed f32x2 FMAs per pixel).
// 4-pixel multi-value butterfly reduction (6 shfl / 4 pixels).
// ---------------------------------------------------------------------------
__global__ void __launch_bounds__(256)
sample_kernel(const float* __restrict__ fmap1,
              const float* __restrict__ cents,
              float* __restrict__ out) {
    __shared__ float Cs[8][104];
    const int warp = threadIdx.x >> 5;
    const int lane = threadIdx.x & 31;
    const int pt = g_perm[blockIdx.x * 8 + warp];   // sorted order
    const int b = pt >> 12;
    const int m = pt & (MM - 1);

    // load q: channels {4*lane+j, 128+4*lane+j}, pack into f32x2 pairs
    const float4* qp = reinterpret_cast<const float4*>(fmap1 + (size_t)pt * CC);
    const float4 q0 = qp[lane];
    const float4 q1 = qp[lane + 32];
    const unsigned long long qA = pk(q0.x, q0.y);
    const unsigned long long qB = pk(q0.z, q0.w);
    const unsigned long long qC = pk(q1.x, q1.y);
    const unsigned long long qD = pk(q1.z, q1.w);

    const float cx = cents[(size_t)pt * 2 + 0];
    const float cy = cents[(size_t)pt * 2 + 1];

    const float* pyr = reinterpret_cast<const float*>(g_pyr4) + (size_t)b * BSTR;
    float* outb = out + (size_t)b * OUTCH * MM + m;

    const int lvlOff[4] = {OFF0, OFF1, OFF2, OFF3};
    const int lvlW[4]   = {64, 32, 16, 8};

    for (int lvl = 0; lvl < NLVL; lvl++) {
        const float sc = 1.0f / (float)(1 << lvl);
        const float cxl = cx * sc, cyl = cy * sc;
        const float fx0 = floorf(cxl), fy0 = floorf(cyl);
        const float wx1 = cxl - fx0, wy1 = cyl - fy0;
        const float wx0 = 1.0f - wx1, wy0 = 1.0f - wy1;
        const int gx0 = (int)fx0 - RAD;
        const int gy0 = (int)fy0 - RAD;
        const int W = lvlW[lvl];
        const float* base = pyr + lvlOff[lvl];

        #pragma unroll
        for (int p = 0; p < 100; p += 4) {
            float s[4];
            #pragma unroll
            for (int k = 0; k < 4; k++) {
                const int u = (p + k) % 10;     // compile-time constants
                const int v = (p + k) / 10;
                const int x = gx0 + u, y = gy0 + v;
                const bool ok = ((unsigned)x < (unsigned)W) &
                                ((unsigned)y < (unsigned)W);
                float sv = 0.0f;
                if (ok) {
                    const float4* f = reinterpret_cast<const float4*>(
                        base + (((size_t)(y * W + x)) << 8));
                    const float4 A  = f[lane];
                    const float4 Bv = f[lane + 32];
                    unsigned long long acc = pk(0.0f, 0.0f);
                    ffma2(acc, pk(A.x, A.y),   qA);
                    ffma2(acc, pk(A.z, A.w),   qB);
                    ffma2(acc, pk(Bv.x, Bv.y), qC);
                    ffma2(acc, pk(Bv.z, Bv.w), qD);
                    const float2 t2 = upk(acc);
                    sv = t2.x + t2.y;
                }
                s[k] = sv;
            }
            // 4-value cross-warp reduction:
            //   lanes 0-7 -> s0, 8-15 -> s1, 16-23 -> s2, 24-31 -> s3
            const unsigned full = 0xffffffffu;
            const bool hi16 = (lane & 16) != 0;
            const bool hi8  = (lane & 8) != 0;
            float rA = __shfl_xor_sync(full, hi16 ? s[0] : s[2], 16);
            float u2 = (hi16 ? s[2] : s[0]) + rA;
            float rB = __shfl_xor_sync(full, hi16 ? s[1] : s[3], 16);
            float v2 = (hi16 ? s[3] : s[1]) + rB;
            float rC = __shfl_xor_sync(full, hi8 ? u2 : v2, 8);
            float w  = (hi8 ? v2 : u2) + rC;
            w += __shfl_xor_sync(full, w, 4);
            w += __shfl_xor_sync(full, w, 2);
            w += __shfl_xor_sync(full, w, 1);
            if ((lane & 7) == 0) Cs[warp][p + (lane >> 3)] = w;
        }
        __syncwarp();

        const float* C = Cs[warp];
        for (int t = lane; t < SIDE * SIDE; t += 32) {
            const int i = t / 9;   // x-offset index
            const int j = t % 9;   // y-offset index
            const float v = wy0 * (wx0 * C[j * 10 + i] + wx1 * C[j * 10 + i + 1])
                          + wy1 * (wx0 * C[(j + 1) * 10 + i] + wx1 * C[(j + 1) * 10 + i + 1]);
            outb[(size_t)(lvl * (SIDE * SIDE) + t) * MM] = v;
        }
        __syncwarp();
    }
}

// ---------------------------------------------------------------------------
extern "C" void kernel_launch(void* const* d_in, const int* in_sizes, int n_in,
                              void* d_out, int out_size) {
    const float* fmap1 = (const float*)d_in[0];   // (B, M, C)
    const float* fmap2 = (const float*)d_in[1];   // (B, C, H, W)
    const float* cents = (const float*)d_in[2];   // (B, M, 2)
    float* out = (float*)d_out;                   // (B, 324, M)

    // Level 0: transpose to pixel-major
    {
        dim3 grid(HH * WW / 32, CC / 32, BB);
        dim3 block(32, 8);
        transpose_l0_kernel<<<grid, block>>>(fmap2);
    }
    // Levels 1..3: iterative 2x2 average pooling
    {
        int tot1 = BB * 32 * 32 * CC;
        pool_kernel<<<(tot1 + 255) / 256, 256>>>(OFF0, OFF1, 64, 32, tot1);
        int tot2 = BB * 16 * 16 * CC;
        pool_kernel<<<(tot2 + 255) / 256, 256>>>(OFF1, OFF2, 32, 16, tot2);
        int tot3 = BB * 8 * 8 * CC;
        pool_kernel<<<(tot3 + 255) / 256, 256>>>(OFF2, OFF3, 16, 8, tot3);
    }
    // Spatial counting sort of points (4x4-pixel bins)
    {
        zero_bins_kernel<<<2, 256>>>();
        count_kernel<<<(BB * MM + 255) / 256, 256>>>(cents);
        scan_kernel<<<1, 512>>>();
        scatter_kernel<<<(BB * MM + 255) / 256, 256>>>(cents);
    }
    // Fused per-point correlation + bilinear sampling (sorted order)
    {
        int nblocks = (BB * MM) / 8;   // 1024 blocks, warp per point
        sample_kernel<<<nblocks, 256>>>(fmap1, cents, out);
    }
}

// round 6
// speedup vs baseline: 1.5275x; 1.5275x over previous
#include <cuda_runtime.h>
#include <cuda_bf16.h>
#include <cstdint>

// Problem constants
#define BB 2
#define MM 4096
#define CC 256
#define HH 64
#define WW 64
#define NLVL 4
#define RAD 4
#define SIDE 9          // 2*RAD+1
#define OUTCH (NLVL * SIDE * SIDE)   // 324

// Pyramid (pixel-major: [b][level][y][x][c]) in float
#define OFF0 0
#define OFF1 (4096 * 256)
#define OFF2 ((4096 + 1024) * 256)
#define OFF3 ((4096 + 1024 + 256) * 256)
#define BSTR ((4096 + 1024 + 256 + 64) * 256)
#define PYR_TOTAL (BB * BSTR)

__device__ float4 g_pyr4[PYR_TOTAL / 4];     // 11.1 MB static scratch
__device__ int g_binCnt[512];
__device__ int g_binOff[512];
__device__ int g_perm[BB * MM];              // sorted position -> point id
__device__ int g_ipos[BB * MM];              // point id -> sorted position
__device__ float g_tmp[BB * MM * OUTCH];     // staged output, [pos][324]

// ---------------------------------------------------------------------------
// packed f32x2 helpers
// ---------------------------------------------------------------------------
__device__ __forceinline__ unsigned long long pk(float x, float y) {
    unsigned long long r;
    asm("mov.b64 %0, {%1, %2};" : "=l"(r) : "f"(x), "f"(y));
    return r;
}
__device__ __forceinline__ float2 upk(unsigned long long v) {
    float2 f;
    asm("mov.b64 {%0, %1}, %2;" : "=f"(f.x), "=f"(f.y) : "l"(v));
    return f;
}
__device__ __forceinline__ void ffma2(unsigned long long& acc,
                                      unsigned long long a,
                                      unsigned long long b) {
    asm("fma.rn.f32x2 %0, %1, %2, %3;" : "=l"(acc) : "l"(a), "l"(b), "l"(acc));
}

// ---------------------------------------------------------------------------
// Kernel A1: transpose fmap2 (b, c, p) -> pyramid level 0 (b, p, c)
// ---------------------------------------------------------------------------
__global__ void transpose_l0_kernel(const float* __restrict__ fmap2) {
    __shared__ float tile[32][33];
    float* g = reinterpret_cast<float*>(g_pyr4);
    int b  = blockIdx.z;
    int c0 = blockIdx.y * 32;
    int p0 = blockIdx.x * 32;
    const float* in_b = fmap2 + (size_t)b * CC * (HH * WW);
    #pragma unroll
    for (int r = threadIdx.y; r < 32; r += 8)
        tile[r][threadIdx.x] = in_b[(size_t)(c0 + r) * (HH * WW) + p0 + threadIdx.x];
    __syncthreads();
    float* out_b = g + (size_t)b * BSTR;
    #pragma unroll
    for (int r = threadIdx.y; r < 32; r += 8)
        out_b[(size_t)(p0 + r) * CC + c0 + threadIdx.x] = tile[threadIdx.x][r];
}

// ---------------------------------------------------------------------------
// Kernel A2: 2x2 average pool, pixel-major
// ---------------------------------------------------------------------------
__global__ void pool_kernel(int inOff, int outOff, int Wi, int Wo, int total) {
    float* g = reinterpret_cast<float*>(g_pyr4);
    int tid = blockIdx.x * blockDim.x + threadIdx.x;
    if (tid >= total) return;
    int c = tid & (CC - 1);
    int idx = tid >> 8;
    int x = idx % Wo; idx /= Wo;
    int y = idx % Wo; idx /= Wo;
    int b = idx;
    const float* ib = g + (size_t)b * BSTR + inOff;
    float v = 0.25f * (ib[((size_t)(2 * y)     * Wi + 2 * x)     * CC + c] +
                       ib[((size_t)(2 * y)     * Wi + 2 * x + 1) * CC + c] +
                       ib[((size_t)(2 * y + 1) * Wi + 2 * x)     * CC + c] +
                       ib[((size_t)(2 * y + 1) * Wi + 2 * x + 1) * CC + c]);
    g[(size_t)b * BSTR + outOff + ((size_t)y * Wo + x) * CC + c] = v;
}

// ---------------------------------------------------------------------------
// Sorting: bin points by 4x4-pixel cell of their centroid (16x16 bins/batch)
// ---------------------------------------------------------------------------
__device__ __forceinline__ int point_bin(const float* cents, int pt) {
    float cx = cents[(size_t)pt * 2 + 0];
    float cy = cents[(size_t)pt * 2 + 1];
    int bx = min(15, max(0, ((int)cx) >> 2));
    int by = min(15, max(0, ((int)cy) >> 2));
    return ((pt >> 12) << 8) + by * 16 + bx;
}

__global__ void zero_bins_kernel() {
    int t = blockIdx.x * blockDim.x + threadIdx.x;
    if (t < 512) g_binCnt[t] = 0;
}

__global__ void count_kernel(const float* __restrict__ cents) {
    int pt = blockIdx.x * blockDim.x + threadIdx.x;
    if (pt >= BB * MM) return;
    atomicAdd(&g_binCnt[point_bin(cents, pt)], 1);
}

__global__ void scan_kernel() {
    __shared__ int s[512];
    int t = threadIdx.x;
    s[t] = g_binCnt[t];
    __syncthreads();
    #pragma unroll
    for (int d = 1; d < 512; d <<= 1) {
        int v = (t >= d) ? s[t - d] : 0;
        __syncthreads();
        s[t] += v;
        __syncthreads();
    }
    g_binOff[t] = s[t] - g_binCnt[t];   // exclusive prefix
}

__global__ void scatter_kernel(const float* __restrict__ cents) {
    int pt = blockIdx.x * blockDim.x + threadIdx.x;
    if (pt >= BB * MM) return;
    int pos = atomicAdd(&g_binOff[point_bin(cents, pt)], 1);
    g_perm[pos] = pt;
    g_ipos[pt] = pos;
}

// ---------------------------------------------------------------------------
// Kernel B: one warp per sorted point. Lane owns 8 channels (2 x float4 ->
// 4 packed f32x2 FMAs per pixel). Block = 8 warps of the same spatial bin,
// kept lockstep with per-level __syncthreads so same-line LDGs merge in L1.
// Writes staged output contiguously at the sorted position.
// ---------------------------------------------------------------------------
__global__ void __launch_bounds__(256)
sample_kernel(const float* __restrict__ fmap1,
              const float* __restrict__ cents,
              float* __restrict__ tmp) {
    __shared__ float Cs[8][104];
    const int warp = threadIdx.x >> 5;
    const int lane = threadIdx.x & 31;
    const int pos = blockIdx.x * 8 + warp;          // sorted position
    const int pt = g_perm[pos];
    const int b = pt >> 12;

    // load q: channels {4*lane+j, 128+4*lane+j}, pack into f32x2 pairs
    const float4* qp = reinterpret_cast<const float4*>(fmap1 + (size_t)pt * CC);
    const float4 q0 = qp[lane];
    const float4 q1 = qp[lane + 32];
    const unsigned long long qA = pk(q0.x, q0.y);
    const unsigned long long qB = pk(q0.z, q0.w);
    const unsigned long long qC = pk(q1.x, q1.y);
    const unsigned long long qD = pk(q1.z, q1.w);

    const float cx = cents[(size_t)pt * 2 + 0];
    const float cy = cents[(size_t)pt * 2 + 1];

    const float* pyr = reinterpret_cast<const float*>(g_pyr4) + (size_t)b * BSTR;
    float* outp = tmp + (size_t)pos * OUTCH;

    const int lvlOff[4] = {OFF0, OFF1, OFF2, OFF3};
    const int lvlW[4]   = {64, 32, 16, 8};

    for (int lvl = 0; lvl < NLVL; lvl++) {
        __syncthreads();   // keep the block's warps lockstep on the shared patch

        const float sc = 1.0f / (float)(1 << lvl);
        const float cxl = cx * sc, cyl = cy * sc;
        const float fx0 = floorf(cxl), fy0 = floorf(cyl);
        const float wx1 = cxl - fx0, wy1 = cyl - fy0;
        const float wx0 = 1.0f - wx1, wy0 = 1.0f - wy1;
        const int gx0 = (int)fx0 - RAD;
        const int gy0 = (int)fy0 - RAD;
        const int W = lvlW[lvl];
        const float* base = pyr + lvlOff[lvl];

        int u = 0, yy = gy0;                        // incremental lattice coords
        for (int p = 0; p < 100; p += 4) {
            float s[4];
            #pragma unroll
            for (int k = 0; k < 4; k++) {
                const int x = gx0 + u;
                const bool ok = ((unsigned)x < (unsigned)W) &
                                ((unsigned)yy < (unsigned)W);
                float sv = 0.0f;
                if (ok) {
                    const float4* f = reinterpret_cast<const float4*>(
                        base + (((size_t)(yy * W + x)) << 8));
                    const float4 A  = f[lane];
                    const float4 Bv = f[lane + 32];
                    unsigned long long acc = pk(0.0f, 0.0f);
                    ffma2(acc, pk(A.x, A.y),   qA);
                    ffma2(acc, pk(A.z, A.w),   qB);
                    ffma2(acc, pk(Bv.x, Bv.y), qC);
                    ffma2(acc, pk(Bv.z, Bv.w), qD);
                    const float2 t2 = upk(acc);
                    sv = t2.x + t2.y;
                }
                s[k] = sv;
                u++; if (u == 10) { u = 0; yy++; }
            }
            // 4-value cross-warp reduction:
            //   lanes 0-7 -> s0, 8-15 -> s1, 16-23 -> s2, 24-31 -> s3
            const unsigned full = 0xffffffffu;
            const bool hi16 = (lane & 16) != 0;
            const bool hi8  = (lane & 8) != 0;
            float rA = __shfl_xor_sync(full, hi16 ? s[0] : s[2], 16);
            float u2 = (hi16 ? s[2] : s[0]) + rA;
            float rB = __shfl_xor_sync(full, hi16 ? s[1] : s[3], 16);
            float v2 = (hi16 ? s[3] : s[1]) + rB;
            float rC = __shfl_xor_sync(full, hi8 ? u2 : v2, 8);
            float w  = (hi8 ? v2 : u2) + rC;
            w += __shfl_xor_sync(full, w, 4);
            w += __shfl_xor_sync(full, w, 2);
            w += __shfl_xor_sync(full, w, 1);
            if ((lane & 7) == 0) Cs[warp][p + (lane >> 3)] = w;
        }
        __syncwarp();

        // bilinear combine 10x10 lattice -> 9x9 outputs, contiguous store
        const float* C = Cs[warp];
        for (int t = lane; t < SIDE * SIDE; t += 32) {
            const int i = t / 9;   // x-offset index
            const int j = t % 9;   // y-offset index
            const float v = wy0 * (wx0 * C[j * 10 + i] + wx1 * C[j * 10 + i + 1])
                          + wy1 * (wx0 * C[(j + 1) * 10 + i] + wx1 * C[(j + 1) * 10 + i + 1]);
            outp[lvl * (SIDE * SIDE) + t] = v;
        }
        __syncwarp();
    }
}

// ---------------------------------------------------------------------------
// Kernel C: unpermute staged output [pos][324] -> final (B, 324, M).
// Coalesced writes; scattered 4B reads (hidden by MLP).
// ---------------------------------------------------------------------------
__global__ void unpermute_kernel(float* __restrict__ out) {
    int tid = blockIdx.x * blockDim.x + threadIdx.x;   // over B*OUTCH*MM
    if (tid >= BB * OUTCH * MM) return;
    const int m  = tid & (MM - 1);
    const int ch = (tid >> 12) % OUTCH;
    const int b  = tid / (OUTCH * MM);
    const int pos = g_ipos[b * MM + m];
    out[tid] = __ldg(&g_tmp[(size_t)pos * OUTCH + ch]);
}

// ---------------------------------------------------------------------------
extern "C" void kernel_launch(void* const* d_in, const int* in_sizes, int n_in,
                              void* d_out, int out_size) {
    const float* fmap1 = (const float*)d_in[0];   // (B, M, C)
    const float* fmap2 = (const float*)d_in[1];   // (B, C, H, W)
    const float* cents = (const float*)d_in[2];   // (B, M, 2)
    float* out = (float*)d_out;                   // (B, 324, M)

    // Level 0: transpose to pixel-major
    {
        dim3 grid(HH * WW / 32, CC / 32, BB);
        dim3 block(32, 8);
        transpose_l0_kernel<<<grid, block>>>(fmap2);
    }
    // Levels 1..3: iterative 2x2 average pooling
    {
        int tot1 = BB * 32 * 32 * CC;
        pool_kernel<<<(tot1 + 255) / 256, 256>>>(OFF0, OFF1, 64, 32, tot1);
        int tot2 = BB * 16 * 16 * CC;
        pool_kernel<<<(tot2 + 255) / 256, 256>>>(OFF1, OFF2, 32, 16, tot2);
        int tot3 = BB * 8 * 8 * CC;
        pool_kernel<<<(tot3 + 255) / 256, 256>>>(OFF2, OFF3, 16, 8, tot3);
    }
    // Spatial counting sort of points (4x4-pixel bins)
    {
        zero_bins_kernel<<<2, 256>>>();
        count_kernel<<<(BB * MM + 255) / 256, 256>>>(cents);
        scan_kernel<<<1, 512>>>();
        scatter_kernel<<<(BB * MM + 255) / 256, 256>>>(cents);
    }
    // Fused per-point correlation + bilinear sampling (sorted, staged output)
    {
        float* tmp;
        cudaGetSymbolAddress((void**)&tmp, g_tmp);
        int nblocks = (BB * MM) / 8;   // 1024 blocks, warp per point
        sample_kernel<<<nblocks, 256>>>(fmap1, cents, tmp);
    }
    // Unpermute to final layout
    {
        int tot = BB * OUTCH * MM;
        unpermute_kernel<<<(tot + 255) / 256, 256>>>(out);
    }
}